// round 10
// baseline (speedup 1.0000x reference)
#include <cuda_runtime.h>
#include <cuda_bf16.h>
#include <math.h>
#include <stdint.h>

#define VOCAB 32000
#define DIM   300
#define KPAD  304     // 19 * 16, zero-padded K
#define B_    128
#define T_    512
#define H_    128
#define G3    384     // 3*H

// Scratch (static device memory, allocation-free):
__device__ float g_proj[2][VOCAB * G3];                 // 98.3 MB
__device__ __nv_bfloat16 g_embH[VOCAB * KPAD];          // 19.5 MB
__device__ __nv_bfloat16 g_embL[VOCAB * KPAD];          // 19.5 MB
__device__ __nv_bfloat16 g_WH[2][G3 * KPAD];            // [dir][n][k] transposed
__device__ __nv_bfloat16 g_WL[2][G3 * KPAD];

// ---- packed f32x2 helpers ---------------------------------------------------
__device__ __forceinline__ unsigned long long ffma2(
    unsigned long long a, unsigned long long b, unsigned long long c) {
    unsigned long long d;
    asm("fma.rn.f32x2 %0, %1, %2, %3;" : "=l"(d) : "l"(a), "l"(b), "l"(c));
    return d;
}
__device__ __forceinline__ unsigned long long pack2(float lo, float hi) {
    unsigned long long r;
    asm("mov.b64 %0, {%1, %2};" : "=l"(r) : "f"(lo), "f"(hi));
    return r;
}
__device__ __forceinline__ float2 unpack2(unsigned long long v) {
    float lo, hi;
    asm("mov.b64 {%0, %1}, %2;" : "=f"(lo), "=f"(hi) : "l"(v));
    return make_float2(lo, hi);
}
__device__ __forceinline__ unsigned long long d_as_ull(double d) {
    return __double_as_longlong(d);
}
__device__ __forceinline__ float fsigmoid(float x) {
    const float e = __expf(-x);
    return __fdividef(1.f, 1.f + e);
}
__device__ __forceinline__ float ftanh(float y) {
    const float e = __expf(-2.f * y);
    const float s = __fdividef(1.f, 1.f + e);
    return fmaf(2.f, s, -1.f);
}

// ---- warp-MMA helpers (baseline PTX, sm_80+) -------------------------------
__device__ __forceinline__ uint32_t smem_u32(const void* p) {
    uint32_t a;
    asm("{ .reg .u64 t; cvta.to.shared.u64 t, %1; cvt.u32.u64 %0, t; }"
        : "=r"(a) : "l"(p));
    return a;
}
__device__ __forceinline__ void ldm_x4(uint32_t& r0, uint32_t& r1,
                                       uint32_t& r2, uint32_t& r3,
                                       uint32_t addr) {
    asm volatile("ldmatrix.sync.aligned.m8n8.x4.shared.b16 {%0,%1,%2,%3}, [%4];"
                 : "=r"(r0), "=r"(r1), "=r"(r2), "=r"(r3) : "r"(addr));
}
__device__ __forceinline__ void mma_bf16(float* c, const uint32_t* a,
                                         const uint32_t* b) {
    asm volatile(
        "mma.sync.aligned.m16n8k16.row.col.f32.bf16.bf16.f32 "
        "{%0,%1,%2,%3}, {%4,%5,%6,%7}, {%8,%9}, {%0,%1,%2,%3};"
        : "+f"(c[0]), "+f"(c[1]), "+f"(c[2]), "+f"(c[3])
        : "r"(a[0]), "r"(a[1]), "r"(a[2]), "r"(a[3]), "r"(b[0]), "r"(b[1]));
}
__device__ __forceinline__ void cp_async16(uint32_t smem_addr,
                                           const void* gptr) {
    asm volatile("cp.async.cg.shared.global [%0], [%1], 16;"
                 :: "r"(smem_addr), "l"(gptr));
}
#define CP_COMMIT() asm volatile("cp.async.commit_group;" ::: "memory")
#define CP_WAIT1()  asm volatile("cp.async.wait_group 1;" ::: "memory")

// convert 8 fp32 -> 8 bf16 hi + 8 bf16 lo packed as uint4 each
__device__ __forceinline__ void cvt8_hilo(const float* v, uint4& H, uint4& L) {
    uint32_t hw[4], lw[4];
    #pragma unroll
    for (int q = 0; q < 4; q++) {
        const __nv_bfloat16 h0 = __float2bfloat16(v[2 * q]);
        const __nv_bfloat16 h1 = __float2bfloat16(v[2 * q + 1]);
        const __nv_bfloat16 l0 = __float2bfloat16(v[2 * q] - __bfloat162float(h0));
        const __nv_bfloat16 l1 = __float2bfloat16(v[2 * q + 1] - __bfloat162float(h1));
        hw[q] = (uint32_t)__bfloat16_as_ushort(h0) |
                ((uint32_t)__bfloat16_as_ushort(h1) << 16);
        lw[q] = (uint32_t)__bfloat16_as_ushort(l0) |
                ((uint32_t)__bfloat16_as_ushort(l1) << 16);
    }
    H = make_uint4(hw[0], hw[1], hw[2], hw[3]);
    L = make_uint4(lw[0], lw[1], lw[2], lw[3]);
}

// ---------------------------------------------------------------------------
// Prep kernels: one-time fp32 -> bf16 hi/lo conversion (K zero-padded to 304)
// ---------------------------------------------------------------------------
__global__ __launch_bounds__(256)
void prep_emb_kernel(const float* __restrict__ emb) {
    const int idx = blockIdx.x * 256 + threadIdx.x;   // one per 8-k group
    const int total = VOCAB * (KPAD / 8);
    if (idx >= total) return;
    const int v = idx / (KPAD / 8);
    const int k0 = (idx % (KPAD / 8)) * 8;
    float val[8];
    const float* src = emb + (size_t)v * DIM + k0;
    if (k0 + 7 < DIM) {
        const float4 f0 = *reinterpret_cast<const float4*>(src);
        const float4 f1 = *reinterpret_cast<const float4*>(src + 4);
        val[0] = f0.x; val[1] = f0.y; val[2] = f0.z; val[3] = f0.w;
        val[4] = f1.x; val[5] = f1.y; val[6] = f1.z; val[7] = f1.w;
    } else {
        #pragma unroll
        for (int j = 0; j < 8; j++)
            val[j] = (k0 + j < DIM) ? src[j] : 0.f;
    }
    uint4 H, L;
    cvt8_hilo(val, H, L);
    *reinterpret_cast<uint4*>(&g_embH[(size_t)v * KPAD + k0]) = H;
    *reinterpret_cast<uint4*>(&g_embL[(size_t)v * KPAD + k0]) = L;
}

__global__ __launch_bounds__(128)
void prep_W_kernel(const float* __restrict__ W_f,
                   const float* __restrict__ W_b) {
    const int idx = blockIdx.x * 128 + threadIdx.x;
    const int total = 2 * G3 * (KPAD / 8);
    if (idx >= total) return;
    const int dir = idx / (G3 * (KPAD / 8));
    const int rem = idx % (G3 * (KPAD / 8));
    const int n   = rem / (KPAD / 8);
    const int k0  = (rem % (KPAD / 8)) * 8;
    const float* W = dir ? W_b : W_f;
    float val[8];
    #pragma unroll
    for (int j = 0; j < 8; j++) {
        const int k = k0 + j;
        val[j] = (k < DIM) ? W[(size_t)k * G3 + n] : 0.f;
    }
    uint4 H, L;
    cvt8_hilo(val, H, L);
    *reinterpret_cast<uint4*>(&g_WH[dir][(size_t)n * KPAD + k0]) = H;
    *reinterpret_cast<uint4*>(&g_WL[dir][(size_t)n * KPAD + k0]) = L;
}

// ---------------------------------------------------------------------------
// Tensor-core projection with 3-stage cp.async pipeline (measured ~156 us
// incl. prep). CTA: 128M x 128N, 8 warps, warp tile 64x32, mma m16n8k16,
// 3-term bf16 split, fp32 accumulators.
// ---------------------------------------------------------------------------
#define NCH 19
#define STG 3

__global__ __launch_bounds__(256, 2)
void proj_mma_kernel(const float* __restrict__ b_f,
                     const float* __restrict__ b_b) {
    __shared__ __align__(16) __nv_bfloat16 Ah[STG][128][16];
    __shared__ __align__(16) __nv_bfloat16 Al[STG][128][16];
    __shared__ __align__(16) __nv_bfloat16 Bh[STG][128][16];  // [n][k]
    __shared__ __align__(16) __nv_bfloat16 Bl[STG][128][16];

    const int dir = blockIdx.z;
    const float* bi = dir ? b_b : b_f;   // row 0 = b_i
    const int vBase = blockIdx.x * 128;
    const int nBase = blockIdx.y * 128;

    const int tid  = threadIdx.x;
    const int lane = tid & 31;
    const int wid  = tid >> 5;
    const int wm   = (wid >> 2) * 64;
    const int wn   = (wid & 3) * 32;

    const int sr = tid >> 1;
    const int sk = (tid & 1) * 8;

    const __nv_bfloat16* embH = g_embH + (size_t)(vBase + sr) * KPAD + sk;
    const __nv_bfloat16* embL = g_embL + (size_t)(vBase + sr) * KPAD + sk;
    const __nv_bfloat16* WHp  = &g_WH[dir][(size_t)(nBase + sr) * KPAD + sk];
    const __nv_bfloat16* WLp  = &g_WL[dir][(size_t)(nBase + sr) * KPAD + sk];

    const uint32_t sAh = smem_u32(&Ah[0][sr][sk]);
    const uint32_t sAl = smem_u32(&Al[0][sr][sk]);
    const uint32_t sBh = smem_u32(&Bh[0][sr][sk]);
    const uint32_t sBl = smem_u32(&Bl[0][sr][sk]);
    const uint32_t stageBytes = 128 * 16 * 2;   // 4096

    auto issue_stage = [&](int ch, int buf) {
        const int kc = ch * 16;
        const uint32_t o = buf * stageBytes;
        cp_async16(sAh + o, embH + kc);
        cp_async16(sAl + o, embL + kc);
        cp_async16(sBh + o, WHp + kc);
        cp_async16(sBl + o, WLp + kc);
    };

    const int grp = lane >> 3;
    const int rin = lane & 7;
    const int a_row_off = (grp & 1) * 8 + rin;
    const int a_col_off = (grp >> 1) * 8;
    const int b_row_off = (grp >> 1) * 8 + rin;
    const int b_col_off = (grp & 1) * 8;

    float acc[4][4][4];
    #pragma unroll
    for (int i = 0; i < 4; i++)
        #pragma unroll
        for (int j = 0; j < 4; j++)
            #pragma unroll
            for (int q = 0; q < 4; q++) acc[i][j][q] = 0.f;

    issue_stage(0, 0); CP_COMMIT();
    issue_stage(1, 1); CP_COMMIT();

    for (int ch = 0; ch < NCH; ch++) {
        const int buf = ch % STG;
        CP_WAIT1();
        __syncthreads();

        if (ch + 2 < NCH) issue_stage(ch + 2, (ch + 2) % STG);
        CP_COMMIT();

        const uint32_t ah = smem_u32(&Ah[buf][0][0]);
        const uint32_t al = smem_u32(&Al[buf][0][0]);
        const uint32_t bh = smem_u32(&Bh[buf][0][0]);
        const uint32_t bl = smem_u32(&Bl[buf][0][0]);

        uint32_t Bhf[2][4], Blf[2][4];
        #pragma unroll
        for (int ip = 0; ip < 2; ip++) {
            const uint32_t boff =
                (uint32_t)((wn + ip * 16 + b_row_off) * 32 + b_col_off * 2);
            ldm_x4(Bhf[ip][0], Bhf[ip][1], Bhf[ip][2], Bhf[ip][3], bh + boff);
            ldm_x4(Blf[ip][0], Blf[ip][1], Blf[ip][2], Blf[ip][3], bl + boff);
        }
        uint32_t Af[4][4];
        #pragma unroll
        for (int im = 0; im < 4; im++) {
            const uint32_t aoff =
                (uint32_t)((wm + im * 16 + a_row_off) * 32 + a_col_off * 2);
            ldm_x4(Af[im][0], Af[im][1], Af[im][2], Af[im][3], ah + aoff);
        }
        #pragma unroll
        for (int im = 0; im < 4; im++)
            #pragma unroll
            for (int ip = 0; ip < 2; ip++) {
                mma_bf16(acc[im][ip * 2 + 0], Af[im], &Bhf[ip][0]);
                mma_bf16(acc[im][ip * 2 + 1], Af[im], &Bhf[ip][2]);
                mma_bf16(acc[im][ip * 2 + 0], Af[im], &Blf[ip][0]);
                mma_bf16(acc[im][ip * 2 + 1], Af[im], &Blf[ip][2]);
            }
        #pragma unroll
        for (int im = 0; im < 4; im++) {
            const uint32_t aoff =
                (uint32_t)((wm + im * 16 + a_row_off) * 32 + a_col_off * 2);
            ldm_x4(Af[im][0], Af[im][1], Af[im][2], Af[im][3], al + aoff);
        }
        #pragma unroll
        for (int im = 0; im < 4; im++)
            #pragma unroll
            for (int ip = 0; ip < 2; ip++) {
                mma_bf16(acc[im][ip * 2 + 0], Af[im], &Bhf[ip][0]);
                mma_bf16(acc[im][ip * 2 + 1], Af[im], &Bhf[ip][2]);
            }
        __syncthreads();
    }

    float* outp = g_proj[dir];
    #pragma unroll
    for (int im = 0; im < 4; im++) {
        const int m = vBase + wm + im * 16 + (lane >> 2);
        #pragma unroll
        for (int in = 0; in < 4; in++) {
            const int n = nBase + wn + in * 8 + (lane & 3) * 2;
            const float b0 = __ldg(&bi[n]);
            const float b1 = __ldg(&bi[n + 1]);
            float* o0 = outp + (size_t)m * G3 + n;
            float* o1 = o0 + 8 * G3;
            *reinterpret_cast<float2*>(o0) =
                make_float2(acc[im][in][0] + b0, acc[im][in][1] + b1);
            *reinterpret_cast<float2*>(o1) =
                make_float2(acc[im][in][2] + b0, acc[im][in][3] + b1);
        }
    }
}

// ---------------------------------------------------------------------------
// GRU scan kernel, K-SPLIT version: 768 threads = 384 columns x 2 K-halves.
// Thread (g, half) holds U[64*half .. 64*half+63][g] (64 regs) and computes a
// partial dot for both batch rows; partials land in recA (half 0, +b_r) and
// recB (half 1); gate threads add the pair. 24 warps/SM for latency hiding.
// ---------------------------------------------------------------------------
__global__ __launch_bounds__(768, 1)
void scan_kernel(const int*   __restrict__ enc,
                 const float* __restrict__ state_fwd,
                 const float* __restrict__ state_back,
                 const float* __restrict__ U_f,
                 const float* __restrict__ b_f,
                 const float* __restrict__ U_b,
                 const float* __restrict__ b_b,
                 float*       __restrict__ out) {
    const int dir = blockIdx.y;
    const int b0  = blockIdx.x * 2;
    const int tid = threadIdx.x;          // 0..767
    const int g    = tid % 384;
    const int half = tid / 384;           // warps 0-11: half 0, 12-23: half 1

    const float* U     = dir ? U_b : U_f;
    const float* br    = (dir ? b_b : b_f) + G3;   // row 1 = b_r
    const float* state = dir ? state_back : state_fwd;
    const float* proj  = g_proj[dir];

    __shared__ __align__(16) float h_sh[2 * H_];
    __shared__ float recA_sh[2 * G3];
    __shared__ float recB_sh[2 * G3];
    __shared__ float xp_sh[2][2 * G3];
    __shared__ int   tok_sh[2][T_];

    // U columns for this thread's K half, packed as f32x2 K-pairs
    unsigned long long Up[32];
    #pragma unroll
    for (int i = 0; i < 32; i++)
        Up[i] = pack2(U[(size_t)(half * 64 + 2 * i) * G3 + g],
                      U[(size_t)(half * 64 + 2 * i + 1) * G3 + g]);
    const float brg = (half == 0) ? br[g] : 0.f;

    for (int i = tid; i < 2 * T_; i += 768) {
        const int b = i >> 9, t = i & (T_ - 1);
        tok_sh[b][t] = enc[(size_t)(b0 + b) * T_ + t];
    }

    if (tid < 256)
        h_sh[tid] = state[(size_t)(b0 + (tid >> 7)) * H_ + (tid & 127)];

    // gate-thread output pointer (tid < 256): (b, j) = (tid>>7, tid&127)
    float* out_ptr = out
        + (size_t)((b0 + (tid >> 7)) * T_ + (dir ? T_ - 1 : 0)) * (2 * H_)
        + dir * H_ + (tid & 127);
    const long out_stride = (dir ? -1 : 1) * (long)(2 * H_);

    // xp preload: one (batch=half, col=g) value per thread
    float pending;   // xp for step s+1
    {
        const int t0 = dir ? (T_ - 1) : 0;
        const int t1 = dir ? (T_ - 2) : 1;
        xp_sh[0][half * G3 + g] =
            proj[(size_t)enc[(size_t)(b0 + half) * T_ + t0] * G3 + g];
        pending = __ldg(&proj[(size_t)enc[(size_t)(b0 + half) * T_ + t1] * G3 + g]);
    }
    __syncthreads();

    int cur = 0;
    for (int s = 0; s < T_; s++) {
        // issue LDG for step s+2 (tokens from SMEM)
        const int s2 = (s + 2 < T_) ? (s + 2) : (T_ - 1);
        const int t2 = dir ? (T_ - 1 - s2) : s2;
        const float fa = __ldg(&proj[(size_t)tok_sh[half][t2] * G3 + g]);

        // flush xp for step s+1 (loaded at step s-1; long since arrived)
        xp_sh[cur ^ 1][half * G3 + g] = pending;

        // partial rec over this thread's K half, both batches
        const double2* hp = reinterpret_cast<const double2*>(h_sh) + half * 16;
        unsigned long long a0 = 0ull, a1 = 0ull;
        #pragma unroll
        for (int j = 0; j < 16; j++) {
            const double2 da = hp[j];        // batch 0
            const double2 db = hp[j + 32];   // batch 1
            a0 = ffma2(d_as_ull(da.x), Up[2 * j],     a0);
            a0 = ffma2(d_as_ull(da.y), Up[2 * j + 1], a0);
            a1 = ffma2(d_as_ull(db.x), Up[2 * j],     a1);
            a1 = ffma2(d_as_ull(db.y), Up[2 * j + 1], a1);
        }
        const float2 r0 = unpack2(a0), r1 = unpack2(a1);
        float* recP = half ? recB_sh : recA_sh;
        recP[g]      = brg + r0.x + r0.y;
        recP[G3 + g] = brg + r1.x + r1.y;

        if (tid < 256) {
            asm volatile("bar.sync 1, 768;" ::: "memory");
            const int b = tid >> 7, j = tid & 127;
            const float* rA = recA_sh + b * G3;
            const float* rB = recB_sh + b * G3;
            const float* xs = xp_sh[cur] + b * G3;
            const float rz = rA[j]       + rB[j];
            const float rr = rA[j + 128] + rB[j + 128];
            const float rh = rA[j + 256] + rB[j + 256];
            const float xz = xs[j], xr = xs[j + 128], xh = xs[j + 256];
            const float z = fsigmoid(xz + rz);
            const float r = fsigmoid(xr + rr);
            const float hh = ftanh(fmaf(r, rh, xh));
            const float hold = h_sh[tid];
            const float hn = fmaf(z, hold - hh, hh);
            h_sh[tid] = hn;
            *out_ptr = hn;
            out_ptr += out_stride;
        } else {
            asm volatile("bar.arrive 1, 768;" ::: "memory");
        }
        __syncthreads();   // h & xp ready for next step

        pending = fa;
        cur ^= 1;
    }

    if (tid < 256) {
        out[(size_t)B_ * T_ * 2 * H_ + (size_t)dir * B_ * H_ +
            (size_t)(b0 + (tid >> 7)) * H_ + (tid & 127)] = h_sh[tid];
    }
}

// ---------------------------------------------------------------------------
// kernel_launch
// ---------------------------------------------------------------------------
extern "C" void kernel_launch(void* const* d_in, const int* in_sizes, int n_in,
                              void* d_out, int out_size) {
    const int*   enc   = (const int*)  d_in[0];
    const float* s_fwd = (const float*)d_in[1];
    const float* s_bck = (const float*)d_in[2];
    const float* emb   = (const float*)d_in[3];
    const float* W_f   = (const float*)d_in[4];
    const float* U_f   = (const float*)d_in[5];
    const float* b_f   = (const float*)d_in[6];
    const float* W_b   = (const float*)d_in[7];
    const float* U_b   = (const float*)d_in[8];
    const float* b_b   = (const float*)d_in[9];
    float* out = (float*)d_out;

    prep_emb_kernel<<<(VOCAB * (KPAD / 8) + 255) / 256, 256>>>(emb);
    prep_W_kernel<<<(2 * G3 * (KPAD / 8) + 127) / 128, 128>>>(W_f, W_b);

    dim3 pgrid(VOCAB / 128, G3 / 128, 2);
    proj_mma_kernel<<<pgrid, 256>>>(b_f, b_b);

    dim3 sgrid(B_ / 2, 2);
    scan_kernel<<<sgrid, 768>>>(enc, s_fwd, s_bck, U_f, b_f, U_b, b_b, out);
}

// round 11
// speedup vs baseline: 1.3971x; 1.3971x over previous
#include <cuda_runtime.h>
#include <cuda_bf16.h>
#include <math.h>
#include <stdint.h>

#define VOCAB 32000
#define DIM   300
#define KPAD  304     // 19 * 16, zero-padded K
#define B_    128
#define T_    512
#define H_    128
#define G3    384     // 3*H

// Scratch (static device memory, allocation-free):
__device__ float g_proj[2][VOCAB * G3];                 // 98.3 MB
__device__ __nv_bfloat16 g_embH[VOCAB * KPAD];          // 19.5 MB
__device__ __nv_bfloat16 g_embL[VOCAB * KPAD];          // 19.5 MB
__device__ __nv_bfloat16 g_WH[2][G3 * KPAD];            // [dir][n][k] transposed
__device__ __nv_bfloat16 g_WL[2][G3 * KPAD];

// ---- packed f32x2 helpers ---------------------------------------------------
__device__ __forceinline__ unsigned long long ffma2(
    unsigned long long a, unsigned long long b, unsigned long long c) {
    unsigned long long d;
    asm("fma.rn.f32x2 %0, %1, %2, %3;" : "=l"(d) : "l"(a), "l"(b), "l"(c));
    return d;
}
__device__ __forceinline__ unsigned long long pack2(float lo, float hi) {
    unsigned long long r;
    asm("mov.b64 %0, {%1, %2};" : "=l"(r) : "f"(lo), "f"(hi));
    return r;
}
__device__ __forceinline__ float2 unpack2(unsigned long long v) {
    float lo, hi;
    asm("mov.b64 {%0, %1}, %2;" : "=f"(lo), "=f"(hi) : "l"(v));
    return make_float2(lo, hi);
}
__device__ __forceinline__ unsigned long long d_as_ull(double d) {
    return __double_as_longlong(d);
}
__device__ __forceinline__ float fsigmoid(float x) {
    const float e = __expf(-x);
    return __fdividef(1.f, 1.f + e);
}
__device__ __forceinline__ float ftanh(float y) {
    const float e = __expf(-2.f * y);
    const float s = __fdividef(1.f, 1.f + e);
    return fmaf(2.f, s, -1.f);
}

// ---- warp-MMA helpers (baseline PTX, sm_80+) -------------------------------
__device__ __forceinline__ uint32_t smem_u32(const void* p) {
    uint32_t a;
    asm("{ .reg .u64 t; cvta.to.shared.u64 t, %1; cvt.u32.u64 %0, t; }"
        : "=r"(a) : "l"(p));
    return a;
}
__device__ __forceinline__ void ldm_x4(uint32_t& r0, uint32_t& r1,
                                       uint32_t& r2, uint32_t& r3,
                                       uint32_t addr) {
    asm volatile("ldmatrix.sync.aligned.m8n8.x4.shared.b16 {%0,%1,%2,%3}, [%4];"
                 : "=r"(r0), "=r"(r1), "=r"(r2), "=r"(r3) : "r"(addr));
}
__device__ __forceinline__ void mma_bf16(float* c, const uint32_t* a,
                                         const uint32_t* b) {
    asm volatile(
        "mma.sync.aligned.m16n8k16.row.col.f32.bf16.bf16.f32 "
        "{%0,%1,%2,%3}, {%4,%5,%6,%7}, {%8,%9}, {%0,%1,%2,%3};"
        : "+f"(c[0]), "+f"(c[1]), "+f"(c[2]), "+f"(c[3])
        : "r"(a[0]), "r"(a[1]), "r"(a[2]), "r"(a[3]), "r"(b[0]), "r"(b[1]));
}
__device__ __forceinline__ void cp_async16(uint32_t smem_addr,
                                           const void* gptr) {
    asm volatile("cp.async.cg.shared.global [%0], [%1], 16;"
                 :: "r"(smem_addr), "l"(gptr));
}
#define CP_COMMIT() asm volatile("cp.async.commit_group;" ::: "memory")
#define CP_WAIT1()  asm volatile("cp.async.wait_group 1;" ::: "memory")

// convert 8 fp32 -> 8 bf16 hi + 8 bf16 lo packed as uint4 each
__device__ __forceinline__ void cvt8_hilo(const float* v, uint4& H, uint4& L) {
    uint32_t hw[4], lw[4];
    #pragma unroll
    for (int q = 0; q < 4; q++) {
        const __nv_bfloat16 h0 = __float2bfloat16(v[2 * q]);
        const __nv_bfloat16 h1 = __float2bfloat16(v[2 * q + 1]);
        const __nv_bfloat16 l0 = __float2bfloat16(v[2 * q] - __bfloat162float(h0));
        const __nv_bfloat16 l1 = __float2bfloat16(v[2 * q + 1] - __bfloat162float(h1));
        hw[q] = (uint32_t)__bfloat16_as_ushort(h0) |
                ((uint32_t)__bfloat16_as_ushort(h1) << 16);
        lw[q] = (uint32_t)__bfloat16_as_ushort(l0) |
                ((uint32_t)__bfloat16_as_ushort(l1) << 16);
    }
    H = make_uint4(hw[0], hw[1], hw[2], hw[3]);
    L = make_uint4(lw[0], lw[1], lw[2], lw[3]);
}

// ---------------------------------------------------------------------------
// Prep kernels: one-time fp32 -> bf16 hi/lo conversion (K zero-padded to 304)
// ---------------------------------------------------------------------------
__global__ __launch_bounds__(256)
void prep_emb_kernel(const float* __restrict__ emb) {
    const int idx = blockIdx.x * 256 + threadIdx.x;   // one per 8-k group
    const int total = VOCAB * (KPAD / 8);
    if (idx >= total) return;
    const int v = idx / (KPAD / 8);
    const int k0 = (idx % (KPAD / 8)) * 8;
    float val[8];
    const float* src = emb + (size_t)v * DIM + k0;
    if (k0 + 7 < DIM) {
        const float4 f0 = *reinterpret_cast<const float4*>(src);
        const float4 f1 = *reinterpret_cast<const float4*>(src + 4);
        val[0] = f0.x; val[1] = f0.y; val[2] = f0.z; val[3] = f0.w;
        val[4] = f1.x; val[5] = f1.y; val[6] = f1.z; val[7] = f1.w;
    } else {
        #pragma unroll
        for (int j = 0; j < 8; j++)
            val[j] = (k0 + j < DIM) ? src[j] : 0.f;
    }
    uint4 H, L;
    cvt8_hilo(val, H, L);
    *reinterpret_cast<uint4*>(&g_embH[(size_t)v * KPAD + k0]) = H;
    *reinterpret_cast<uint4*>(&g_embL[(size_t)v * KPAD + k0]) = L;
}

__global__ __launch_bounds__(128)
void prep_W_kernel(const float* __restrict__ W_f,
                   const float* __restrict__ W_b) {
    const int idx = blockIdx.x * 128 + threadIdx.x;
    const int total = 2 * G3 * (KPAD / 8);
    if (idx >= total) return;
    const int dir = idx / (G3 * (KPAD / 8));
    const int rem = idx % (G3 * (KPAD / 8));
    const int n   = rem / (KPAD / 8);
    const int k0  = (rem % (KPAD / 8)) * 8;
    const float* W = dir ? W_b : W_f;
    float val[8];
    #pragma unroll
    for (int j = 0; j < 8; j++) {
        const int k = k0 + j;
        val[j] = (k < DIM) ? W[(size_t)k * G3 + n] : 0.f;
    }
    uint4 H, L;
    cvt8_hilo(val, H, L);
    *reinterpret_cast<uint4*>(&g_WH[dir][(size_t)n * KPAD + k0]) = H;
    *reinterpret_cast<uint4*>(&g_WL[dir][(size_t)n * KPAD + k0]) = L;
}

// ---------------------------------------------------------------------------
// Tensor-core projection, 2-stage cp.async pipeline, 48-byte tile row pitch
// (conflict-free ldmatrix: rows 0..7 hit disjoint bank groups).
// CTA: 128M x 128N, 8 warps, warp tile 64x32, mma m16n8k16,
// 3-term bf16 split (hi*hi + hi*lo + lo*hi), fp32 accumulators.
// SMEM: 2 stages x 4 tiles x 128 x 48B = 49152 B (48 KB), 2 CTAs/SM.
// ---------------------------------------------------------------------------
#define NCH 19
#define ROWB 48                         // bytes per tile row (32 data + 16 pad)
#define TILEB (128 * ROWB)              // 6144 B
#define STAGEB (4 * TILEB)              // 24576 B

__global__ __launch_bounds__(256, 2)
void proj_mma_kernel(const float* __restrict__ b_f,
                     const float* __restrict__ b_b) {
    __shared__ __align__(16) char smem[2 * STAGEB];   // 48 KB

    const int dir = blockIdx.z;
    const float* bi = dir ? b_b : b_f;   // row 0 = b_i
    const int vBase = blockIdx.x * 128;
    const int nBase = blockIdx.y * 128;

    const int tid  = threadIdx.x;
    const int lane = tid & 31;
    const int wid  = tid >> 5;
    const int wm   = (wid >> 2) * 64;
    const int wn   = (wid & 3) * 32;

    // cp.async mapping: 2 threads per row, 16B (8 bf16) each
    const int sr = tid >> 1;             // 0..127
    const int sk = (tid & 1) * 8;        // element offset 0 / 8

    const __nv_bfloat16* embH = g_embH + (size_t)(vBase + sr) * KPAD + sk;
    const __nv_bfloat16* embL = g_embL + (size_t)(vBase + sr) * KPAD + sk;
    const __nv_bfloat16* WHp  = &g_WH[dir][(size_t)(nBase + sr) * KPAD + sk];
    const __nv_bfloat16* WLp  = &g_WL[dir][(size_t)(nBase + sr) * KPAD + sk];

    const uint32_t smem0 = smem_u32(smem);
    const uint32_t dst   = smem0 + (uint32_t)(sr * ROWB + sk * 2);

    auto issue_stage = [&](int ch, int buf) {
        const int kc = ch * 16;
        const uint32_t o = (uint32_t)(buf * STAGEB);
        cp_async16(dst + o + 0 * TILEB, embH + kc);
        cp_async16(dst + o + 1 * TILEB, embL + kc);
        cp_async16(dst + o + 2 * TILEB, WHp + kc);
        cp_async16(dst + o + 3 * TILEB, WLp + kc);
    };

    // ldmatrix lane geometry
    const int grp = lane >> 3;
    const int rin = lane & 7;
    const int a_row_off = (grp & 1) * 8 + rin;
    const int a_col_off = (grp >> 1) * 8;
    const int b_row_off = (grp >> 1) * 8 + rin;
    const int b_col_off = (grp & 1) * 8;

    float acc[4][4][4];
    #pragma unroll
    for (int i = 0; i < 4; i++)
        #pragma unroll
        for (int j = 0; j < 4; j++)
            #pragma unroll
            for (int q = 0; q < 4; q++) acc[i][j][q] = 0.f;

    // prologue: stages 0,1 in flight
    issue_stage(0, 0); CP_COMMIT();
    issue_stage(1, 1); CP_COMMIT();

    for (int ch = 0; ch < NCH; ch++) {
        const int buf = ch & 1;
        CP_WAIT1();            // stage ch arrived (ch+1 may still be in flight)
        __syncthreads();

        const uint32_t base = smem0 + (uint32_t)(buf * STAGEB);
        const uint32_t ah = base + 0 * TILEB;
        const uint32_t al = base + 1 * TILEB;
        const uint32_t bh = base + 2 * TILEB;
        const uint32_t bl = base + 3 * TILEB;

        uint32_t Bhf[2][4], Blf[2][4];
        #pragma unroll
        for (int ip = 0; ip < 2; ip++) {
            const uint32_t boff =
                (uint32_t)((wn + ip * 16 + b_row_off) * ROWB + b_col_off * 2);
            ldm_x4(Bhf[ip][0], Bhf[ip][1], Bhf[ip][2], Bhf[ip][3], bh + boff);
            ldm_x4(Blf[ip][0], Blf[ip][1], Blf[ip][2], Blf[ip][3], bl + boff);
        }
        uint32_t Af[4][4];
        #pragma unroll
        for (int im = 0; im < 4; im++) {
            const uint32_t aoff =
                (uint32_t)((wm + im * 16 + a_row_off) * ROWB + a_col_off * 2);
            ldm_x4(Af[im][0], Af[im][1], Af[im][2], Af[im][3], ah + aoff);
        }
        // term 0: Ahi*Bhi ; term 1: Ahi*Blo
        #pragma unroll
        for (int im = 0; im < 4; im++)
            #pragma unroll
            for (int ip = 0; ip < 2; ip++) {
                mma_bf16(acc[im][ip * 2 + 0], Af[im], &Bhf[ip][0]);
                mma_bf16(acc[im][ip * 2 + 1], Af[im], &Bhf[ip][2]);
                mma_bf16(acc[im][ip * 2 + 0], Af[im], &Blf[ip][0]);
                mma_bf16(acc[im][ip * 2 + 1], Af[im], &Blf[ip][2]);
            }
        // term 2: Alo*Bhi
        #pragma unroll
        for (int im = 0; im < 4; im++) {
            const uint32_t aoff =
                (uint32_t)((wm + im * 16 + a_row_off) * ROWB + a_col_off * 2);
            ldm_x4(Af[im][0], Af[im][1], Af[im][2], Af[im][3], al + aoff);
        }
        #pragma unroll
        for (int im = 0; im < 4; im++)
            #pragma unroll
            for (int ip = 0; ip < 2; ip++) {
                mma_bf16(acc[im][ip * 2 + 0], Af[im], &Bhf[ip][0]);
                mma_bf16(acc[im][ip * 2 + 1], Af[im], &Bhf[ip][2]);
            }
        __syncthreads();       // all reads of buf done before refill

        // refill this buffer with stage ch+2 (covered by compute of ch+1)
        if (ch + 2 < NCH) issue_stage(ch + 2, buf);
        CP_COMMIT();           // commit (possibly empty) to keep accounting
    }

    // ---- epilogue: add bias, store fp32 ----
    float* outp = g_proj[dir];
    #pragma unroll
    for (int im = 0; im < 4; im++) {
        const int m = vBase + wm + im * 16 + (lane >> 2);
        #pragma unroll
        for (int in = 0; in < 4; in++) {
            const int n = nBase + wn + in * 8 + (lane & 3) * 2;
            const float b0 = __ldg(&bi[n]);
            const float b1 = __ldg(&bi[n + 1]);
            float* o0 = outp + (size_t)m * G3 + n;
            float* o1 = o0 + 8 * G3;
            *reinterpret_cast<float2*>(o0) =
                make_float2(acc[im][in][0] + b0, acc[im][in][1] + b1);
            *reinterpret_cast<float2*>(o1) =
                make_float2(acc[im][in][2] + b0, acc[im][in][3] + b1);
        }
    }
}

// ---------------------------------------------------------------------------
// GRU scan kernel (exact R9 version, measured 542-545 us).
// ---------------------------------------------------------------------------
__global__ __launch_bounds__(384, 1)
void scan_kernel(const int*   __restrict__ enc,
                 const float* __restrict__ state_fwd,
                 const float* __restrict__ state_back,
                 const float* __restrict__ U_f,
                 const float* __restrict__ b_f,
                 const float* __restrict__ U_b,
                 const float* __restrict__ b_b,
                 float*       __restrict__ out) {
    const int dir = blockIdx.y;
    const int b0  = blockIdx.x * 2;
    const int g   = threadIdx.x;          // 0..383

    const float* U     = dir ? U_b : U_f;
    const float* br    = (dir ? b_b : b_f) + G3;   // row 1 = b_r
    const float* state = dir ? state_back : state_fwd;
    const float* proj  = g_proj[dir];

    __shared__ __align__(16) float h_sh[2 * H_];
    __shared__ float rec_sh[2 * G3];
    __shared__ float xp_sh[2][2 * G3];
    __shared__ int   tok_sh[2][T_];

    unsigned long long Up[64];
    #pragma unroll
    for (int i = 0; i < 64; i++)
        Up[i] = pack2(U[(size_t)(2 * i) * G3 + g],
                      U[(size_t)(2 * i + 1) * G3 + g]);
    const float brg = br[g];

    for (int i = g; i < 2 * T_; i += 384) {
        const int b = i >> 9, t = i & (T_ - 1);
        tok_sh[b][t] = enc[(size_t)(b0 + b) * T_ + t];
    }

    const int gb = g >> 7, gj = g & 127;          // valid for g < 256
    float* out_ptr = out + (size_t)((b0 + gb) * T_ + (dir ? T_ - 1 : 0)) * (2 * H_)
                   + dir * H_ + gj;
    const long out_stride = (dir ? -1 : 1) * (long)(2 * H_);

    if (g < 256)
        h_sh[gb * H_ + gj] = state[(size_t)(b0 + gb) * H_ + gj];

    float bufA[2], bufB[2];
    {
        const int t0 = dir ? (T_ - 1) : 0;
        const int t1 = dir ? (T_ - 2) : 1;
        xp_sh[0][0 * G3 + g] = proj[(size_t)enc[(size_t)b0 * T_ + t0] * G3 + g];
        xp_sh[0][1 * G3 + g] = proj[(size_t)enc[(size_t)(b0 + 1) * T_ + t0] * G3 + g];
        bufA[1] = __ldg(&proj[(size_t)enc[(size_t)b0 * T_ + t1] * G3 + g]);
        bufB[1] = __ldg(&proj[(size_t)enc[(size_t)(b0 + 1) * T_ + t1] * G3 + g]);
        bufA[0] = 0.f; bufB[0] = 0.f;
    }
    __syncthreads();

    int cur = 0;
    #pragma unroll 2
    for (int s = 0; s < T_; s++) {
        const int s2 = (s + 2 < T_) ? (s + 2) : (T_ - 1);
        const int t2 = dir ? (T_ - 1 - s2) : s2;
        const float fa = __ldg(&proj[(size_t)tok_sh[0][t2] * G3 + g]);
        const float fb = __ldg(&proj[(size_t)tok_sh[1][t2] * G3 + g]);

        xp_sh[cur ^ 1][0 * G3 + g] = bufA[(s + 1) & 1];
        xp_sh[cur ^ 1][1 * G3 + g] = bufB[(s + 1) & 1];

        unsigned long long a0 = 0ull, a1 = 0ull;
        unsigned long long a2 = 0ull, a3 = 0ull;
        const double2* h0p = reinterpret_cast<const double2*>(h_sh);
        const double2* h1p = reinterpret_cast<const double2*>(h_sh + H_);
        #pragma unroll
        for (int j = 0; j < 32; j++) {
            const double2 da = h0p[j];
            const double2 db = h1p[j];
            a0 = ffma2(d_as_ull(da.x), Up[2 * j],     a0);
            a1 = ffma2(d_as_ull(da.y), Up[2 * j + 1], a1);
            a2 = ffma2(d_as_ull(db.x), Up[2 * j],     a2);
            a3 = ffma2(d_as_ull(db.y), Up[2 * j + 1], a3);
        }
        const float2 r0 = unpack2(a0), r1 = unpack2(a1);
        const float2 r2 = unpack2(a2), r3 = unpack2(a3);
        rec_sh[0 * G3 + g] = brg + ((r0.x + r0.y) + (r1.x + r1.y));
        rec_sh[1 * G3 + g] = brg + ((r2.x + r2.y) + (r3.x + r3.y));

        if (g < 256) {
            asm volatile("bar.sync 1, 384;" ::: "memory");
            const float* rs = rec_sh + gb * G3;
            const float* xs = xp_sh[cur] + gb * G3;
            const float rz = rs[gj], rr = rs[gj + 128], rh = rs[gj + 256];
            const float xz = xs[gj], xr = xs[gj + 128], xh = xs[gj + 256];
            const float z = fsigmoid(xz + rz);
            const float r = fsigmoid(xr + rr);
            const float hh = ftanh(fmaf(r, rh, xh));
            const float hold = h_sh[gb * H_ + gj];
            const float hn = z * hold + (1.f - z) * hh;
            h_sh[gb * H_ + gj] = hn;
            *out_ptr = hn;
            out_ptr += out_stride;
        } else {
            asm volatile("bar.arrive 1, 384;" ::: "memory");
        }
        __syncthreads();

        bufA[s & 1] = fa;
        bufB[s & 1] = fb;
        cur ^= 1;
    }

    if (g < 256) {
        out[(size_t)B_ * T_ * 2 * H_ + (size_t)dir * B_ * H_ +
            (size_t)(b0 + gb) * H_ + gj] = h_sh[gb * H_ + gj];
    }
}

// ---------------------------------------------------------------------------
// kernel_launch
// ---------------------------------------------------------------------------
extern "C" void kernel_launch(void* const* d_in, const int* in_sizes, int n_in,
                              void* d_out, int out_size) {
    const int*   enc   = (const int*)  d_in[0];
    const float* s_fwd = (const float*)d_in[1];
    const float* s_bck = (const float*)d_in[2];
    const float* emb   = (const float*)d_in[3];
    const float* W_f   = (const float*)d_in[4];
    const float* U_f   = (const float*)d_in[5];
    const float* b_f   = (const float*)d_in[6];
    const float* W_b   = (const float*)d_in[7];
    const float* U_b   = (const float*)d_in[8];
    const float* b_b   = (const float*)d_in[9];
    float* out = (float*)d_out;

    prep_emb_kernel<<<(VOCAB * (KPAD / 8) + 255) / 256, 256>>>(emb);
    prep_W_kernel<<<(2 * G3 * (KPAD / 8) + 127) / 128, 128>>>(W_f, W_b);

    dim3 pgrid(VOCAB / 128, G3 / 128, 2);
    proj_mma_kernel<<<pgrid, 256>>>(b_f, b_b);

    dim3 sgrid(B_ / 2, 2);
    scan_kernel<<<sgrid, 384>>>(enc, s_fwd, s_bck, U_f, b_f, U_b, b_b, out);
}